// round 11
// baseline (speedup 1.0000x reference)
#include <cuda_runtime.h>
#include <cuda_bf16.h>
#include <math.h>
#include <stdint.h>

#define NPTS 4096
#define DS 48
#define DA 16
#define DF 64
#define TB 128
#define NTILE (NPTS / TB)      /* 32 */
#define NFULL (NTILE * NTILE)  /* 1024 full tiles */
#define NTRI  528              /* upper-tri tiles */
#define NB1 2048               /* coarse bins over [0,16] */
#define SC1 128.0f             /* NB1/16 */
#define NBF 8192               /* fine bins in refine pass */

// ---------------- device scratch ----------------
__device__ __nv_bfloat16 g_hiA[(size_t)NPTS * DF], g_loA[(size_t)NPTS * DF];
__device__ __nv_bfloat16 g_hiB[(size_t)NPTS * DF], g_loB[(size_t)NPTS * DF];
__device__ float  g_x2[NPTS];
__device__ float  g_y2[NPTS];
__device__ float  g_hcoarse[2 * NB1];
__device__ float  g_hfine[2 * NBF];
__device__ double g_below[2];
__device__ double g_scal[8];   // 0 Wsum,1 EWsum,2/3 lo/width ae,4/5 lo/width ee,6 g1,7 g2
__device__ float  g_Sae[NPTS];
__device__ float  g_Saa[NPTS];

// ---------------- mma / ldmatrix helpers ----------------
#define MMA_AB(d, A, b0, b1)                                                \
    asm volatile(                                                           \
        "mma.sync.aligned.m16n8k16.row.col.f32.bf16.bf16.f32 "              \
        "{%0,%1,%2,%3}, {%4,%5,%6,%7}, {%8,%9}, {%0,%1,%2,%3};"             \
        : "+f"((d)[0]), "+f"((d)[1]), "+f"((d)[2]), "+f"((d)[3])            \
        : "r"((A)[0]), "r"((A)[1]), "r"((A)[2]), "r"((A)[3]), "r"(b0), "r"(b1))

__device__ __forceinline__ void ldsm4(uint32_t a, uint32_t d[4]) {
    asm volatile("ldmatrix.sync.aligned.m8n8.x4.shared.b16 {%0,%1,%2,%3}, [%4];"
                 : "=r"(d[0]), "=r"(d[1]), "=r"(d[2]), "=r"(d[3]) : "r"(a));
}

#define SWO(r, kc) ((uint32_t)(r) * 128u + (((uint32_t)(kc)) ^ (((uint32_t)(r) & 7u) << 4)))
#define TILE_BYTES 16384

// tri decode: t in [0, 528) -> (by, bx) upper-tri tile
__device__ __forceinline__ void tri_decode(int t, int& by, int& bx) {
    by = 0;
    while (t >= NTILE - by) { t -= NTILE - by; by++; }
    bx = by + t;
}

// ---------------- staging ----------------
__device__ __forceinline__ void stage_one(char* dst, const __nv_bfloat16* src,
                                          int row0, int rstride, int tid, int nrows) {
    const uint4* p = (const uint4*)src;
    for (int idx = tid; idx < nrows * 8; idx += 256) {
        int r = idx >> 3, c = idx & 7;
        uint32_t off = (uint32_t)r * 128u + (((uint32_t)c * 16u) ^ (((uint32_t)r & 7u) << 4));
        *(uint4*)(dst + off) = p[(size_t)(row0 + r * rstride) * 8 + c];
    }
}

// ---------------- mainloop ----------------
template <int MF, bool THREE>
__device__ __forceinline__ void mma_loop(uint32_t sAh, uint32_t sAl,
                                         uint32_t sBh, uint32_t sBl,
                                         int tid, float acc[4][4][4]) {
    const int lane = tid & 31, warp = tid >> 5;
    const int wr = warp >> 2, wc = warp & 3;

    #pragma unroll
    for (int mf = 0; mf < MF; mf++)
        #pragma unroll
        for (int nf = 0; nf < 4; nf++)
            #pragma unroll
            for (int u = 0; u < 4; u++) acc[mf][nf][u] = 0.f;

    const int aRow = lane & 15;
    const int aKc  = (lane >> 4) << 4;
    const int bRow = ((lane & 16) >> 1) + (lane & 7);
    const int bKc  = (lane & 8) ? 16 : 0;

    #pragma unroll
    for (int ks = 0; ks < 4; ks++) {
        const int kc0 = ks * 32;
        uint32_t BH[2][4], BL[2][4];
        #pragma unroll
        for (int p = 0; p < 2; p++) {
            uint32_t off = SWO(wc * 32 + p * 16 + bRow, kc0 + bKc);
            ldsm4(sBh + off, BH[p]);
            if (THREE) ldsm4(sBl + off, BL[p]);
        }
        #pragma unroll
        for (int mf = 0; mf < MF; mf++) {
            uint32_t off = SWO(wr * (MF * 16) + mf * 16 + aRow, kc0 + aKc);
            uint32_t AH[4], AL[4];
            ldsm4(sAh + off, AH);
            if (THREE) ldsm4(sAl + off, AL);
            #pragma unroll
            for (int p = 0; p < 2; p++) {
                MMA_AB(acc[mf][2 * p],     AH, BH[p][0], BH[p][1]);
                MMA_AB(acc[mf][2 * p + 1], AH, BH[p][2], BH[p][3]);
                if (THREE) {
                    MMA_AB(acc[mf][2 * p],     AH, BL[p][0], BL[p][1]);
                    MMA_AB(acc[mf][2 * p],     AL, BH[p][0], BH[p][1]);
                    MMA_AB(acc[mf][2 * p + 1], AH, BL[p][2], BL[p][3]);
                    MMA_AB(acc[mf][2 * p + 1], AL, BH[p][2], BH[p][3]);
                }
            }
        }
    }
}

// ---------------- convert inputs + row norms + zero accumulators ----------------
__global__ void k_cvt(const float* __restrict__ ss, const float* __restrict__ aa_,
                      const float* __restrict__ es, const float* __restrict__ ea) {
    __shared__ float part[8];
    int tid = threadIdx.x;
    int gid = blockIdx.x * 256 + tid;
    if (gid < 2 * NB1) g_hcoarse[gid] = 0.f;
    if (gid < 2 * NBF) g_hfine[gid]   = 0.f;
    if (gid < NPTS)  { g_Saa[gid] = 0.f; g_Sae[gid] = 0.f; }
    if (gid < 2)       g_below[gid]   = 0.0;

    int gr = blockIdx.x * 4 + (tid >> 6);
    int k  = tid & 63;
    bool isA = (gr < NPTS);
    int r = isA ? gr : gr - NPTS;
    const float* sp = isA ? ss : es;
    const float* ap = isA ? aa_ : ea;
    __nv_bfloat16* hi = isA ? g_hiA : g_hiB;
    __nv_bfloat16* lo = isA ? g_loA : g_loB;

    float v = (k < DS) ? sp[(size_t)r * DS + k] : ap[(size_t)r * DA + (k - DS)];
    __nv_bfloat16 h = __float2bfloat16(v);
    hi[(size_t)r * DF + k] = h;
    lo[(size_t)r * DF + k] = __float2bfloat16(v - __bfloat162float(h));

    float sq = v * v;
    #pragma unroll
    for (int off = 16; off; off >>= 1) sq += __shfl_xor_sync(0xFFFFFFFF, sq, off);
    if ((tid & 31) == 0) part[tid >> 5] = sq;
    __syncthreads();
    if ((tid & 63) == 0) {
        float s = part[(tid >> 5)] + part[(tid >> 5) + 1];
        if (isA) g_x2[r] = s; else g_y2[r] = s;
    }
}

// ---------------- weight sums (double, deterministic) ----------------
__global__ void k_wsum(const float* __restrict__ w, const float* __restrict__ ew) {
    __shared__ double sh[1024];
    int tid = threadIdx.x;
    double s1 = 0.0, s2 = 0.0;
    for (int i = tid; i < NPTS; i += 1024) { s1 += w[i]; s2 += ew[i]; }
    sh[tid] = s1; __syncthreads();
    for (int off = 512; off; off >>= 1) { if (tid < off) sh[tid] += sh[tid + off]; __syncthreads(); }
    if (tid == 0) g_scal[0] = sh[0];
    __syncthreads();
    sh[tid] = s2; __syncthreads();
    for (int off = 512; off; off >>= 1) { if (tid < off) sh[tid] += sh[tid + off]; __syncthreads(); }
    if (tid == 0) g_scal[1] = sh[0];
}

// ---------------- sampled coarse hist via hi-only MMA, M=64 tiles ----------------
#define HOF_X2    0
#define HOF_WX    256
#define HOF_Y2    512
#define HOF_WY    1024
#define HOF_HIST  1536
#define HOF_TILES 17920
#define SMEM_HS   (HOF_TILES + 8192 + 16384)   /* 42496 */

__global__ void __launch_bounds__(256) k_hist_sampled(
    const float* __restrict__ w, const float* __restrict__ ew)
{
    extern __shared__ __align__(128) char smem[];
    int tid = threadIdx.x;
    bool ae = (blockIdx.z == 0);
    int col0 = blockIdx.x * TB;
    int sbase = blockIdx.y * 64;

    const __nv_bfloat16* Ah = ae ? g_hiA : g_hiB;
    const float* x2p = ae ? g_x2 : g_y2;
    const float* wxp = ae ? w : ew;

    float* shh = (float*)(smem + HOF_HIST);
    for (int i = tid; i < 2 * NB1; i += 256) shh[i] = 0.f;

    stage_one(smem + HOF_TILES,        Ah,    sbase * 16, 16, tid, 64);
    stage_one(smem + HOF_TILES + 8192, g_hiB, col0,       1,  tid, 128);
    if (tid < 64) {
        ((float*)(smem + HOF_X2))[tid] = x2p[(sbase + tid) * 16];
        ((float*)(smem + HOF_WX))[tid] = wxp[(sbase + tid) * 16];
    }
    if (tid < TB) {
        ((float*)(smem + HOF_Y2))[tid] = g_y2[col0 + tid];
        ((float*)(smem + HOF_WY))[tid] = ew[col0 + tid];
    }
    __syncthreads();

    uint32_t sT = (uint32_t)__cvta_generic_to_shared(smem) + HOF_TILES;
    float acc[4][4][4];
    mma_loop<2, false>(sT, 0, sT + 8192, 0, tid, acc);

    const int lane = tid & 31, warp = tid >> 5;
    const int wr = warp >> 2, wc = warp & 3;
    const int g = lane >> 2, t = lane & 3;
    const float* x2s = (const float*)(smem + HOF_X2);
    const float* wxs = (const float*)(smem + HOF_WX);
    const float* y2s = (const float*)(smem + HOF_Y2);
    const float* wys = (const float*)(smem + HOF_WY);
    float* myh = shh + (warp & 1) * NB1;

    #pragma unroll
    for (int mf = 0; mf < 2; mf++) {
        int r0 = wr * 32 + mf * 16 + g;
        float x0 = x2s[r0], x1 = x2s[r0 + 8];
        float wx0 = wxs[r0], wx1 = wxs[r0 + 8];
        #pragma unroll
        for (int nf = 0; nf < 4; nf++) {
            int c0 = wc * 32 + nf * 8 + 2 * t;
            float y0 = y2s[c0], y1 = y2s[c0 + 1];
            float wy0 = wys[c0], wy1 = wys[c0 + 1];
            float d00 = fmaxf(x0 + y0 - 2.f * acc[mf][nf][0], 0.f) * (1.f / DF);
            float d01 = fmaxf(x0 + y1 - 2.f * acc[mf][nf][1], 0.f) * (1.f / DF);
            float d10 = fmaxf(x1 + y0 - 2.f * acc[mf][nf][2], 0.f) * (1.f / DF);
            float d11 = fmaxf(x1 + y1 - 2.f * acc[mf][nf][3], 0.f) * (1.f / DF);
            atomicAdd(&myh[min((int)(d00 * SC1), NB1 - 1)], wx0 * wy0);
            atomicAdd(&myh[min((int)(d01 * SC1), NB1 - 1)], wx0 * wy1);
            atomicAdd(&myh[min((int)(d10 * SC1), NB1 - 1)], wx1 * wy0);
            atomicAdd(&myh[min((int)(d11 * SC1), NB1 - 1)], wx1 * wy1);
        }
    }
    __syncthreads();
    float* hist = g_hcoarse + (ae ? 0 : NB1);
    for (int i = tid; i < NB1; i += 256) {
        float v = shh[i] + shh[i + NB1];
        if (v != 0.f) atomicAdd(&hist[i], v);
    }
}

// ---------------- scan coarse hist -> window (±16 bins) ----------------
__global__ void k_scan0() {
    int which = blockIdx.x;
    const float* h = g_hcoarse + which * NB1;
    __shared__ double part[256];
    int tid = threadIdx.x;
    double loc[8], s = 0.0;
    #pragma unroll
    for (int i = 0; i < 8; i++) { loc[i] = h[tid * 8 + i]; s += loc[i]; }
    part[tid] = s; __syncthreads();
    for (int off = 1; off < 256; off <<= 1) {
        double v = (tid >= off) ? part[tid - off] : 0.0;
        __syncthreads();
        part[tid] += v;
        __syncthreads();
    }
    double T = 0.5 * part[255];
    double c = tid ? part[tid - 1] : 0.0;
    int b = -1;
    #pragma unroll
    for (int i = 0; i < 8; i++) {
        double nc = c + loc[i];
        if (b < 0 && c < T && nc >= T) b = tid * 8 + i;
        c = nc;
    }
    if (b >= 0) {
        int blo = b > 16 ? b - 16 : 0;
        int bhi = b + 17 > NB1 ? NB1 : b + 17;
        g_scal[2 + 2 * which] = blo * (16.0 / NB1);
        g_scal[3 + 2 * which] = (bhi - blo) * (16.0 / NB1);
    }
}

// ---------------- refine via hi-only MMA: ae full (1024) + ee upper-tri (528) ----------------
#define ROF_X2    0
#define ROF_Y2    512
#define ROF_WX    1024
#define ROF_WY    1536
#define ROF_HIST  2048
#define ROF_TILES 34816
#define SMEM_RF   (ROF_TILES + 2 * TILE_BYTES)   /* 67584 */

__global__ void __launch_bounds__(256) k_refine_mma(
    const float* __restrict__ w, const float* __restrict__ ew)
{
    extern __shared__ __align__(128) char smem[];
    int tid = threadIdx.x;
    int b = blockIdx.x;
    bool ae = (b < NFULL);
    int row0, col0;
    if (ae) { row0 = (b >> 5) * TB; col0 = (b & 31) * TB; }
    else { int by, bx; tri_decode(b - NFULL, by, bx); row0 = by * TB; col0 = bx * TB; }
    bool diag = (!ae) && (row0 == col0);
    int which = ae ? 0 : 1;

    const __nv_bfloat16* Ah = ae ? g_hiA : g_hiB;
    const float* x2p = ae ? g_x2 : g_y2;
    const float* wxp = ae ? w : ew;

    float* shh = (float*)(smem + ROF_HIST);
    for (int i = tid; i < NBF; i += 256) shh[i] = 0.f;

    stage_one(smem + ROF_TILES,              Ah,    row0, 1, tid, 128);
    stage_one(smem + ROF_TILES + TILE_BYTES, g_hiB, col0, 1, tid, 128);
    if (tid < TB) {
        ((float*)(smem + ROF_X2))[tid] = x2p[row0 + tid];
        ((float*)(smem + ROF_WX))[tid] = wxp[row0 + tid];
        ((float*)(smem + ROF_Y2))[tid] = g_y2[col0 + tid];
        ((float*)(smem + ROF_WY))[tid] = ew[col0 + tid];
    }
    __syncthreads();

    uint32_t sT = (uint32_t)__cvta_generic_to_shared(smem) + ROF_TILES;
    float acc[4][4][4];
    mma_loop<4, false>(sT, 0, sT + TILE_BYTES, 0, tid, acc);

    const int lane = tid & 31, warp = tid >> 5;
    const int wr = warp >> 2, wc = warp & 3;
    const int g = lane >> 2, t = lane & 3;
    const float* x2s = (const float*)(smem + ROF_X2);
    const float* y2s = (const float*)(smem + ROF_Y2);
    const float* wxs = (const float*)(smem + ROF_WX);
    const float* wys = (const float*)(smem + ROF_WY);

    float lo    = (float)g_scal[2 + 2 * which];
    float scale = (float)((double)NBF / g_scal[3 + 2 * which]);
    float wmul = ae ? 1.f : 2.f;     // tri tiles count twice (except diagonal handling)
    float bacc = 0.f;

    #pragma unroll
    for (int mf = 0; mf < 4; mf++) {
        int r0 = wr * 64 + mf * 16 + g;
        float x0 = x2s[r0], x1 = x2s[r0 + 8];
        float wx0 = wxs[r0] * wmul, wx1 = wxs[r0 + 8] * wmul;
        #pragma unroll
        for (int nf = 0; nf < 4; nf++) {
            int c0 = wc * 32 + nf * 8 + 2 * t;
            float y0 = y2s[c0], y1 = y2s[c0 + 1];
            float wy0 = wys[c0], wy1 = wys[c0 + 1];
            float dd[4], wt[4];
            dd[0] = fmaxf(x0 + y0 - 2.f * acc[mf][nf][0], 0.f) * (1.f / DF); wt[0] = wx0 * wy0;
            dd[1] = fmaxf(x0 + y1 - 2.f * acc[mf][nf][1], 0.f) * (1.f / DF); wt[1] = wx0 * wy1;
            dd[2] = fmaxf(x1 + y0 - 2.f * acc[mf][nf][2], 0.f) * (1.f / DF); wt[2] = wx1 * wy0;
            dd[3] = fmaxf(x1 + y1 - 2.f * acc[mf][nf][3], 0.f) * (1.f / DF); wt[3] = wx1 * wy1;
            if (diag) {
                // element (ri, cj): keep upper incl diagonal; diag weight = 1x (wt has 2x)
                int ri[4] = {r0, r0, r0 + 8, r0 + 8};
                int cj[4] = {c0, c0 + 1, c0, c0 + 1};
                #pragma unroll
                for (int u = 0; u < 4; u++) {
                    if (cj[u] < ri[u]) wt[u] = 0.f;
                    else if (cj[u] == ri[u]) wt[u] *= 0.5f;
                }
            }
            #pragma unroll
            for (int u = 0; u < 4; u++) {
                if (wt[u] != 0.f) {
                    if (dd[u] < lo) bacc += wt[u];
                    else {
                        int bb = (int)((dd[u] - lo) * scale);
                        if (bb < NBF) atomicAdd(&shh[bb], wt[u]);
                    }
                }
            }
        }
    }
    __shared__ float red[256];
    red[tid] = bacc; __syncthreads();
    for (int off = 128; off; off >>= 1) {
        if (tid < off) red[tid] += red[tid + off];
        __syncthreads();
    }
    if (tid == 0) atomicAdd(&g_below[which], (double)red[0]);
    float* hist = g_hfine + which * NBF;
    for (int i = tid; i < NBF; i += 256) {
        float v = shh[i];
        if (v != 0.f) atomicAdd(&hist[i], v);
    }
}

// ---------------- scan fine hist -> g ----------------
__global__ void k_scanF() {
    int which = blockIdx.x;
    const float* h = g_hfine + which * NBF;
    __shared__ double part[1024];
    int tid = threadIdx.x;
    double loc[8], s = 0.0;
    #pragma unroll
    for (int i = 0; i < 8; i++) { loc[i] = h[tid * 8 + i]; s += loc[i]; }
    part[tid] = s; __syncthreads();
    for (int off = 1; off < 1024; off <<= 1) {
        double v = (tid >= off) ? part[tid - off] : 0.0;
        __syncthreads();
        part[tid] += v;
        __syncthreads();
    }
    double Wtot = (which == 0) ? g_scal[0] * g_scal[1] : g_scal[1] * g_scal[1];
    double T = 0.5 * Wtot - g_below[which];
    double lo = g_scal[2 + 2 * which], wdt = g_scal[3 + 2 * which];
    double c = tid ? part[tid - 1] : 0.0;
    int b = -1;
    #pragma unroll
    for (int i = 0; i < 8; i++) {
        double nc = c + loc[i];
        if (b < 0 && c < T && nc >= T) b = tid * 8 + i;
        c = nc;
    }
    if (tid == 0 && T <= 0.0) b = 0;
    if (tid == 1023 && T > 0.0 && part[1023] < T && b < 0) b = NBF - 1;
    if (b >= 0) {
        double tt = lo + (b + 0.5) * (wdt / NBF);
        g_scal[6 + which] = 1.0 / (tt + 1e-8);
    }
}

// ---------------- final: ae full (1024) + aa upper-tri (528, row+col sums) ----------------
#define FOF_X2    0
#define FOF_Y2    512
#define FOF_W     1024     /* col weights */
#define FOF_WR    1536     /* row weights */
#define FOF_RS    2048
#define FOF_CS    2560
#define FOF_TILES 3072
#define SMEM_FIN  (FOF_TILES + 4 * TILE_BYTES)   /* 68608 */

__global__ void __launch_bounds__(256) k_final(
    const float* __restrict__ w, const float* __restrict__ ew)
{
    extern __shared__ __align__(128) char smem[];
    int tid = threadIdx.x;
    int b = blockIdx.x;
    bool ae = (b < NFULL);
    int row0, col0;
    if (ae) { row0 = (b >> 5) * TB; col0 = (b & 31) * TB; }
    else { int by, bx; tri_decode(b - NFULL, by, bx); row0 = by * TB; col0 = bx * TB; }
    bool offd = (!ae) && (row0 != col0);

    const __nv_bfloat16* Bh = ae ? g_hiB : g_hiA;
    const __nv_bfloat16* Bl = ae ? g_loB : g_loA;
    const float* y2p = ae ? g_y2 : g_x2;
    const float* wyp = ae ? ew : w;

    stage_one(smem + FOF_TILES,                  g_hiA, row0, 1, tid, 128);
    stage_one(smem + FOF_TILES + TILE_BYTES,     g_loA, row0, 1, tid, 128);
    stage_one(smem + FOF_TILES + 2 * TILE_BYTES, Bh,    col0, 1, tid, 128);
    stage_one(smem + FOF_TILES + 3 * TILE_BYTES, Bl,    col0, 1, tid, 128);
    if (tid < TB) {
        ((float*)(smem + FOF_X2))[tid] = g_x2[row0 + tid];
        ((float*)(smem + FOF_Y2))[tid] = y2p[col0 + tid];
        ((float*)(smem + FOF_W))[tid]  = wyp[col0 + tid];
        ((float*)(smem + FOF_WR))[tid] = w[row0 + tid];
        ((float*)(smem + FOF_RS))[tid] = 0.f;
        ((float*)(smem + FOF_CS))[tid] = 0.f;
    }
    __syncthreads();

    uint32_t sT = (uint32_t)__cvta_generic_to_shared(smem) + FOF_TILES;
    float acc[4][4][4];
    mma_loop<4, true>(sT, sT + TILE_BYTES, sT + 2 * TILE_BYTES, sT + 3 * TILE_BYTES, tid, acc);

    const int lane = tid & 31, warp = tid >> 5;
    const int wr = warp >> 2, wc = warp & 3;
    const int g = lane >> 2, t = lane & 3;
    const float* x2s = (const float*)(smem + FOF_X2);
    const float* y2s = (const float*)(smem + FOF_Y2);
    const float* ws  = (const float*)(smem + FOF_W);
    const float* wrs = (const float*)(smem + FOF_WR);
    float* rowsum = (float*)(smem + FOF_RS);
    float* colsum = (float*)(smem + FOF_CS);

    float G1 = (float)g_scal[6], G2 = (float)g_scal[7];

    #pragma unroll
    for (int mf = 0; mf < 4; mf++) {
        int r0 = wr * 64 + mf * 16 + g;
        float x0 = x2s[r0], x1 = x2s[r0 + 8];
        float wr0 = wrs[r0], wr1 = wrs[r0 + 8];
        float p0 = 0.f, p1 = 0.f;
        #pragma unroll
        for (int nf = 0; nf < 4; nf++) {
            int c0 = wc * 32 + nf * 8 + 2 * t;
            float y0 = y2s[c0], y1 = y2s[c0 + 1];
            float w0 = ws[c0],  w1 = ws[c0 + 1];
            float d00 = fmaxf(x0 + y0 - 2.f * acc[mf][nf][0], 0.f) * (1.f / DF);
            float d01 = fmaxf(x0 + y1 - 2.f * acc[mf][nf][1], 0.f) * (1.f / DF);
            float d10 = fmaxf(x1 + y0 - 2.f * acc[mf][nf][2], 0.f) * (1.f / DF);
            float d11 = fmaxf(x1 + y1 - 2.f * acc[mf][nf][3], 0.f) * (1.f / DF);
            float K00 = __expf(-G1 * d00) + __expf(-G2 * d00);
            float K01 = __expf(-G1 * d01) + __expf(-G2 * d01);
            float K10 = __expf(-G1 * d10) + __expf(-G2 * d10);
            float K11 = __expf(-G1 * d11) + __expf(-G2 * d11);
            p0 += K00 * w0 + K01 * w1;
            p1 += K10 * w0 + K11 * w1;
            if (offd) {
                atomicAdd(&colsum[c0],     K00 * wr0 + K10 * wr1);
                atomicAdd(&colsum[c0 + 1], K01 * wr0 + K11 * wr1);
            }
        }
        atomicAdd(&rowsum[r0], p0);
        atomicAdd(&rowsum[r0 + 8], p1);
    }
    __syncthreads();
    if (tid < TB) {
        float* Sout = ae ? g_Sae : g_Saa;
        atomicAdd(&Sout[row0 + tid], rowsum[tid]);
        if (offd) atomicAdd(&g_Saa[col0 + tid], colsum[tid]);
    }
}

// ---------------- final combine ----------------
__global__ void k_combine(const float* __restrict__ w, float* __restrict__ out) {
    int i = blockIdx.x * blockDim.x + threadIdx.x;
    if (i < NPTS) {
        float Ws  = (float)g_scal[0];
        float EWs = (float)g_scal[1];
        out[i] = (w[i] / Ws) * (g_Sae[i] / EWs - g_Saa[i] / Ws);
    }
}

// ---------------- host launcher ----------------
extern "C" void kernel_launch(void* const* d_in, const int* in_sizes, int n_in,
                              void* d_out, int out_size)
{
    const float* state   = (const float*)d_in[0];
    const float* action  = (const float*)d_in[1];
    const float* estate  = (const float*)d_in[2];
    const float* eaction = (const float*)d_in[3];
    const float* w       = (const float*)d_in[4];
    const float* ew      = (const float*)d_in[5];
    float* out = (float*)d_out;

    cudaFuncSetAttribute(k_hist_sampled, cudaFuncAttributeMaxDynamicSharedMemorySize, SMEM_HS);
    cudaFuncSetAttribute(k_refine_mma,   cudaFuncAttributeMaxDynamicSharedMemorySize, SMEM_RF);
    cudaFuncSetAttribute(k_final,        cudaFuncAttributeMaxDynamicSharedMemorySize, SMEM_FIN);

    dim3 ghs(NTILE, 4, 2);

    k_cvt<<<2048, 256>>>(state, action, estate, eaction);
    k_wsum<<<1, 1024>>>(w, ew);

    k_hist_sampled<<<ghs, 256, SMEM_HS>>>(w, ew);
    k_scan0<<<2, 256>>>();

    k_refine_mma<<<NFULL + NTRI, 256, SMEM_RF>>>(w, ew);
    k_scanF<<<2, 1024>>>();

    k_final<<<NFULL + NTRI, 256, SMEM_FIN>>>(w, ew);

    k_combine<<<16, 256>>>(w, out);
}

// round 13
// speedup vs baseline: 1.1230x; 1.1230x over previous
#include <cuda_runtime.h>
#include <cuda_fp16.h>
#include <math.h>
#include <stdint.h>

#define NPTS 4096
#define DS 48
#define DA 16
#define DF 64
#define TB 128
#define NTILE (NPTS / TB)      /* 32 */
#define NB1 2048               /* coarse bins over [0,16] */
#define SC1 128.0f             /* NB1/16 */
#define NBF 8192               /* fine bins in refine pass */

// ---------------- device scratch ----------------
__device__ __half g_hA[(size_t)NPTS * DF];    // fp16(concat(state,action))
__device__ __half g_hB[(size_t)NPTS * DF];    // fp16(concat(estate,eaction))
__device__ float  g_x2[NPTS];
__device__ float  g_y2[NPTS];
__device__ float  g_hcoarse[2 * NB1];
__device__ float  g_hfine[2 * NBF];
__device__ double g_below[2];
__device__ double g_scal[8];   // 0 Wsum,1 EWsum,2/3 lo/width ae,4/5 lo/width ee,6 g1,7 g2
__device__ float  g_Sae[NPTS];
__device__ float  g_Saa[NPTS];

// ---------------- mma / ldmatrix helpers (fp16 in, fp32 accum) ----------------
#define MMA_AB(d, A, b0, b1)                                                \
    asm volatile(                                                           \
        "mma.sync.aligned.m16n8k16.row.col.f32.f16.f16.f32 "                \
        "{%0,%1,%2,%3}, {%4,%5,%6,%7}, {%8,%9}, {%0,%1,%2,%3};"             \
        : "+f"((d)[0]), "+f"((d)[1]), "+f"((d)[2]), "+f"((d)[3])            \
        : "r"((A)[0]), "r"((A)[1]), "r"((A)[2]), "r"((A)[3]), "r"(b0), "r"(b1))

__device__ __forceinline__ void ldsm4(uint32_t a, uint32_t d[4]) {
    asm volatile("ldmatrix.sync.aligned.m8n8.x4.shared.b16 {%0,%1,%2,%3}, [%4];"
                 : "=r"(d[0]), "=r"(d[1]), "=r"(d[2]), "=r"(d[3]) : "r"(a));
}

#define SWO(r, kc) ((uint32_t)(r) * 128u + (((uint32_t)(kc)) ^ (((uint32_t)(r) & 7u) << 4)))
#define TILE_BYTES 16384

// ---------------- staging: global (row-major 128B rows) -> swizzled smem tile ----------------
__device__ __forceinline__ void stage_one(char* dst, const __half* src,
                                          int row0, int rstride, int tid, int nrows) {
    const uint4* p = (const uint4*)src;
    for (int idx = tid; idx < nrows * 8; idx += 256) {
        int r = idx >> 3, c = idx & 7;
        uint32_t off = (uint32_t)r * 128u + (((uint32_t)c * 16u) ^ (((uint32_t)r & 7u) << 4));
        *(uint4*)(dst + off) = p[(size_t)(row0 + r * rstride) * 8 + c];
    }
}

// ---------------- mainloop: single-product fp16 mma ----------------
template <int MF>
__device__ __forceinline__ void mma_loop(uint32_t sA, uint32_t sB,
                                         int tid, float acc[4][4][4]) {
    const int lane = tid & 31, warp = tid >> 5;
    const int wr = warp >> 2, wc = warp & 3;

    #pragma unroll
    for (int mf = 0; mf < MF; mf++)
        #pragma unroll
        for (int nf = 0; nf < 4; nf++)
            #pragma unroll
            for (int u = 0; u < 4; u++) acc[mf][nf][u] = 0.f;

    const int aRow = lane & 15;
    const int aKc  = (lane >> 4) << 4;
    const int bRow = ((lane & 16) >> 1) + (lane & 7);
    const int bKc  = (lane & 8) ? 16 : 0;

    #pragma unroll
    for (int ks = 0; ks < 4; ks++) {
        const int kc0 = ks * 32;
        uint32_t BH[2][4];
        #pragma unroll
        for (int p = 0; p < 2; p++) {
            uint32_t off = SWO(wc * 32 + p * 16 + bRow, kc0 + bKc);
            ldsm4(sB + off, BH[p]);
        }
        #pragma unroll
        for (int mf = 0; mf < MF; mf++) {
            uint32_t off = SWO(wr * (MF * 16) + mf * 16 + aRow, kc0 + aKc);
            uint32_t AH[4];
            ldsm4(sA + off, AH);
            #pragma unroll
            for (int p = 0; p < 2; p++) {
                MMA_AB(acc[mf][2 * p],     AH, BH[p][0], BH[p][1]);
                MMA_AB(acc[mf][2 * p + 1], AH, BH[p][2], BH[p][3]);
            }
        }
    }
}

// ---------------- convert inputs to fp16 + row norms + zero accumulators ----------------
__global__ void k_cvt(const float* __restrict__ ss, const float* __restrict__ aa_,
                      const float* __restrict__ es, const float* __restrict__ ea) {
    __shared__ float cvt_part[8];
    int tid = threadIdx.x;
    int gid = blockIdx.x * 256 + tid;
    if (gid < 2 * NB1) g_hcoarse[gid] = 0.f;
    if (gid < 2 * NBF) g_hfine[gid]   = 0.f;
    if (gid < NPTS)  { g_Saa[gid] = 0.f; g_Sae[gid] = 0.f; }
    if (gid < 2)       g_below[gid]   = 0.0;

    int gr = blockIdx.x * 4 + (tid >> 6);
    int k  = tid & 63;
    bool isA = (gr < NPTS);
    int r = isA ? gr : gr - NPTS;
    const float* sp = isA ? ss : es;
    const float* ap = isA ? aa_ : ea;
    __half* hp = isA ? g_hA : g_hB;

    float v = (k < DS) ? sp[(size_t)r * DS + k] : ap[(size_t)r * DA + (k - DS)];
    hp[(size_t)r * DF + k] = __float2half(v);

    float sq = v * v;
    #pragma unroll
    for (int off = 16; off; off >>= 1) sq += __shfl_xor_sync(0xFFFFFFFF, sq, off);
    if ((tid & 31) == 0) cvt_part[tid >> 5] = sq;
    __syncthreads();
    if ((tid & 63) == 0) {
        float s = cvt_part[(tid >> 5)] + cvt_part[(tid >> 5) + 1];
        if (isA) g_x2[r] = s; else g_y2[r] = s;
    }
}

// ---------------- weight sums (double) ----------------
__global__ void k_wsum(const float* __restrict__ w, const float* __restrict__ ew) {
    __shared__ double sh[1024];
    int tid = threadIdx.x;
    double s1 = 0.0, s2 = 0.0;
    for (int i = tid; i < NPTS; i += 1024) { s1 += w[i]; s2 += ew[i]; }
    sh[tid] = s1; __syncthreads();
    for (int off = 512; off; off >>= 1) { if (tid < off) sh[tid] += sh[tid + off]; __syncthreads(); }
    if (tid == 0) g_scal[0] = sh[0];
    __syncthreads();
    sh[tid] = s2; __syncthreads();
    for (int off = 512; off; off >>= 1) { if (tid < off) sh[tid] += sh[tid + off]; __syncthreads(); }
    if (tid == 0) g_scal[1] = sh[0];
}

// ---------------- sampled coarse hist via fp16 MMA, M=64 tiles ----------------
#define HOF_X2    0
#define HOF_WX    256
#define HOF_Y2    512
#define HOF_WY    1024
#define HOF_HIST  1536
#define HOF_TILES 17920
#define SMEM_HS   (HOF_TILES + 8192 + 16384)   /* 42496 */

__global__ void __launch_bounds__(256) k_hist_sampled(
    const float* __restrict__ w, const float* __restrict__ ew)
{
    extern __shared__ __align__(128) char smem[];
    int tid = threadIdx.x;
    bool ae = (blockIdx.z == 0);
    int col0 = blockIdx.x * TB;
    int sbase = blockIdx.y * 64;

    const __half* Ah = ae ? g_hA : g_hB;
    const float* x2p = ae ? g_x2 : g_y2;
    const float* wxp = ae ? w : ew;

    float* shh = (float*)(smem + HOF_HIST);
    for (int i = tid; i < 2 * NB1; i += 256) shh[i] = 0.f;

    stage_one(smem + HOF_TILES,        Ah,   sbase * 16, 16, tid, 64);
    stage_one(smem + HOF_TILES + 8192, g_hB, col0,       1,  tid, 128);
    if (tid < 64) {
        ((float*)(smem + HOF_X2))[tid] = x2p[(sbase + tid) * 16];
        ((float*)(smem + HOF_WX))[tid] = wxp[(sbase + tid) * 16];
    }
    if (tid < TB) {
        ((float*)(smem + HOF_Y2))[tid] = g_y2[col0 + tid];
        ((float*)(smem + HOF_WY))[tid] = ew[col0 + tid];
    }
    __syncthreads();

    uint32_t sT = (uint32_t)__cvta_generic_to_shared(smem) + HOF_TILES;
    float acc[4][4][4];
    mma_loop<2>(sT, sT + 8192, tid, acc);

    const int lane = tid & 31, warp = tid >> 5;
    const int wr = warp >> 2, wc = warp & 3;
    const int g = lane >> 2, t = lane & 3;
    const float* x2s = (const float*)(smem + HOF_X2);
    const float* wxs = (const float*)(smem + HOF_WX);
    const float* y2s = (const float*)(smem + HOF_Y2);
    const float* wys = (const float*)(smem + HOF_WY);
    float* myh = shh + (warp & 1) * NB1;

    #pragma unroll
    for (int mf = 0; mf < 2; mf++) {
        int r0 = wr * 32 + mf * 16 + g;
        float x0 = x2s[r0], x1 = x2s[r0 + 8];
        float wx0 = wxs[r0], wx1 = wxs[r0 + 8];
        #pragma unroll
        for (int nf = 0; nf < 4; nf++) {
            int c0 = wc * 32 + nf * 8 + 2 * t;
            float y0 = y2s[c0], y1 = y2s[c0 + 1];
            float wy0 = wys[c0], wy1 = wys[c0 + 1];
            float d00 = fmaxf(x0 + y0 - 2.f * acc[mf][nf][0], 0.f) * (1.f / DF);
            float d01 = fmaxf(x0 + y1 - 2.f * acc[mf][nf][1], 0.f) * (1.f / DF);
            float d10 = fmaxf(x1 + y0 - 2.f * acc[mf][nf][2], 0.f) * (1.f / DF);
            float d11 = fmaxf(x1 + y1 - 2.f * acc[mf][nf][3], 0.f) * (1.f / DF);
            atomicAdd(&myh[min((int)(d00 * SC1), NB1 - 1)], wx0 * wy0);
            atomicAdd(&myh[min((int)(d01 * SC1), NB1 - 1)], wx0 * wy1);
            atomicAdd(&myh[min((int)(d10 * SC1), NB1 - 1)], wx1 * wy0);
            atomicAdd(&myh[min((int)(d11 * SC1), NB1 - 1)], wx1 * wy1);
        }
    }
    __syncthreads();
    float* hist = g_hcoarse + (ae ? 0 : NB1);
    for (int i = tid; i < NB1; i += 256) {
        float v = shh[i] + shh[i + NB1];
        if (v != 0.f) atomicAdd(&hist[i], v);
    }
}

// ---------------- scan coarse hist -> window (±16 bins) ----------------
__global__ void k_scan0() {
    int which = blockIdx.x;
    const float* h = g_hcoarse + which * NB1;
    __shared__ double part[256];
    int tid = threadIdx.x;
    double loc[8], s = 0.0;
    #pragma unroll
    for (int i = 0; i < 8; i++) { loc[i] = h[tid * 8 + i]; s += loc[i]; }
    part[tid] = s; __syncthreads();
    for (int off = 1; off < 256; off <<= 1) {
        double v = (tid >= off) ? part[tid - off] : 0.0;
        __syncthreads();
        part[tid] += v;
        __syncthreads();
    }
    double T = 0.5 * part[255];
    double c = tid ? part[tid - 1] : 0.0;
    int b = -1;
    #pragma unroll
    for (int i = 0; i < 8; i++) {
        double nc = c + loc[i];
        if (b < 0 && c < T && nc >= T) b = tid * 8 + i;
        c = nc;
    }
    if (b >= 0) {
        int blo = b > 16 ? b - 16 : 0;
        int bhi = b + 17 > NB1 ? NB1 : b + 17;
        g_scal[2 + 2 * which] = blo * (16.0 / NB1);
        g_scal[3 + 2 * which] = (bhi - blo) * (16.0 / NB1);
    }
}

// ---------------- refine via fp16 MMA recompute: below-mass + fine hist ----------------
#define ROF_X2    0
#define ROF_Y2    512
#define ROF_WX    1024
#define ROF_WY    1536
#define ROF_HIST  2048
#define ROF_TILES 34816
#define SMEM_RF   (ROF_TILES + 2 * TILE_BYTES)   /* 67584 */

__global__ void __launch_bounds__(256) k_refine_mma(
    const float* __restrict__ w, const float* __restrict__ ew)
{
    extern __shared__ __align__(128) char smem[];
    int tid = threadIdx.x;
    bool ae = (blockIdx.z == 0);
    int row0 = blockIdx.y * TB, col0 = blockIdx.x * TB;

    const __half* Ah = ae ? g_hA : g_hB;
    const float* x2p = ae ? g_x2 : g_y2;
    const float* wxp = ae ? w : ew;
    int which = ae ? 0 : 1;

    float* shh = (float*)(smem + ROF_HIST);
    for (int i = tid; i < NBF; i += 256) shh[i] = 0.f;

    stage_one(smem + ROF_TILES,              Ah,   row0, 1, tid, 128);
    stage_one(smem + ROF_TILES + TILE_BYTES, g_hB, col0, 1, tid, 128);
    if (tid < TB) {
        ((float*)(smem + ROF_X2))[tid] = x2p[row0 + tid];
        ((float*)(smem + ROF_WX))[tid] = wxp[row0 + tid];
        ((float*)(smem + ROF_Y2))[tid] = g_y2[col0 + tid];
        ((float*)(smem + ROF_WY))[tid] = ew[col0 + tid];
    }
    __syncthreads();

    uint32_t sT = (uint32_t)__cvta_generic_to_shared(smem) + ROF_TILES;
    float acc[4][4][4];
    mma_loop<4>(sT, sT + TILE_BYTES, tid, acc);

    const int lane = tid & 31, warp = tid >> 5;
    const int wr = warp >> 2, wc = warp & 3;
    const int g = lane >> 2, t = lane & 3;
    const float* x2s = (const float*)(smem + ROF_X2);
    const float* y2s = (const float*)(smem + ROF_Y2);
    const float* wxs = (const float*)(smem + ROF_WX);
    const float* wys = (const float*)(smem + ROF_WY);

    float lo    = (float)g_scal[2 + 2 * which];
    float scale = (float)((double)NBF / g_scal[3 + 2 * which]);
    float bacc = 0.f;

    #pragma unroll
    for (int mf = 0; mf < 4; mf++) {
        int r0 = wr * 64 + mf * 16 + g;
        float x0 = x2s[r0], x1 = x2s[r0 + 8];
        float wx0 = wxs[r0], wx1 = wxs[r0 + 8];
        #pragma unroll
        for (int nf = 0; nf < 4; nf++) {
            int c0 = wc * 32 + nf * 8 + 2 * t;
            float y0 = y2s[c0], y1 = y2s[c0 + 1];
            float wy0 = wys[c0], wy1 = wys[c0 + 1];
            float dd[4], wt[4];
            dd[0] = fmaxf(x0 + y0 - 2.f * acc[mf][nf][0], 0.f) * (1.f / DF); wt[0] = wx0 * wy0;
            dd[1] = fmaxf(x0 + y1 - 2.f * acc[mf][nf][1], 0.f) * (1.f / DF); wt[1] = wx0 * wy1;
            dd[2] = fmaxf(x1 + y0 - 2.f * acc[mf][nf][2], 0.f) * (1.f / DF); wt[2] = wx1 * wy0;
            dd[3] = fmaxf(x1 + y1 - 2.f * acc[mf][nf][3], 0.f) * (1.f / DF); wt[3] = wx1 * wy1;
            #pragma unroll
            for (int u = 0; u < 4; u++) {
                if (dd[u] < lo) bacc += wt[u];
                else {
                    int b = (int)((dd[u] - lo) * scale);
                    if (b < NBF) atomicAdd(&shh[b], wt[u]);
                }
            }
        }
    }
    __shared__ float red[256];
    red[tid] = bacc; __syncthreads();
    for (int off = 128; off; off >>= 1) {
        if (tid < off) red[tid] += red[tid + off];
        __syncthreads();
    }
    if (tid == 0) atomicAdd(&g_below[which], (double)red[0]);
    float* hist = g_hfine + which * NBF;
    for (int i = tid; i < NBF; i += 256) {
        float v = shh[i];
        if (v != 0.f) atomicAdd(&hist[i], v);
    }
}

// ---------------- scan fine hist -> g ----------------
__global__ void k_scanF() {
    int which = blockIdx.x;
    const float* h = g_hfine + which * NBF;
    __shared__ double part[1024];
    int tid = threadIdx.x;
    double loc[8], s = 0.0;
    #pragma unroll
    for (int i = 0; i < 8; i++) { loc[i] = h[tid * 8 + i]; s += loc[i]; }
    part[tid] = s; __syncthreads();
    for (int off = 1; off < 1024; off <<= 1) {
        double v = (tid >= off) ? part[tid - off] : 0.0;
        __syncthreads();
        part[tid] += v;
        __syncthreads();
    }
    double Wtot = (which == 0) ? g_scal[0] * g_scal[1] : g_scal[1] * g_scal[1];
    double T = 0.5 * Wtot - g_below[which];
    double lo = g_scal[2 + 2 * which], wdt = g_scal[3 + 2 * which];
    double c = tid ? part[tid - 1] : 0.0;
    int b = -1;
    #pragma unroll
    for (int i = 0; i < 8; i++) {
        double nc = c + loc[i];
        if (b < 0 && c < T && nc >= T) b = tid * 8 + i;
        c = nc;
    }
    if (tid == 0 && T <= 0.0) b = 0;
    if (tid == 1023 && T > 0.0 && part[1023] < T && b < 0) b = NBF - 1;
    if (b >= 0) {
        double tt = lo + (b + 0.5) * (wdt / NBF);
        g_scal[6 + which] = 1.0 / (tt + 1e-8);
    }
}

// ---------------- final: fp16 MMA recompute + K-weighted row sums (z=0 ae, z=1 aa) ---------
#define FOF_X2    0
#define FOF_Y2    512
#define FOF_W     1024
#define FOF_RS    1536
#define FOF_TILES 2048
#define SMEM_FIN  (FOF_TILES + 2 * TILE_BYTES)   /* 34816 */

__global__ void __launch_bounds__(256) k_final(
    const float* __restrict__ w, const float* __restrict__ ew)
{
    extern __shared__ __align__(128) char smem[];
    int tid = threadIdx.x;
    int row0 = blockIdx.y * TB, col0 = blockIdx.x * TB;
    bool ae = (blockIdx.z == 0);

    const __half* Bh = ae ? g_hB : g_hA;
    const float* y2p = ae ? g_y2 : g_x2;
    const float* wyp = ae ? ew : w;

    stage_one(smem + FOF_TILES,              g_hA, row0, 1, tid, 128);
    stage_one(smem + FOF_TILES + TILE_BYTES, Bh,   col0, 1, tid, 128);
    if (tid < TB) {
        ((float*)(smem + FOF_X2))[tid] = g_x2[row0 + tid];
        ((float*)(smem + FOF_Y2))[tid] = y2p[col0 + tid];
        ((float*)(smem + FOF_W))[tid]  = wyp[col0 + tid];
        ((float*)(smem + FOF_RS))[tid] = 0.f;
    }
    __syncthreads();

    uint32_t sT = (uint32_t)__cvta_generic_to_shared(smem) + FOF_TILES;
    float acc[4][4][4];
    mma_loop<4>(sT, sT + TILE_BYTES, tid, acc);

    const int lane = tid & 31, warp = tid >> 5;
    const int wr = warp >> 2, wc = warp & 3;
    const int g = lane >> 2, t = lane & 3;
    const float* x2s = (const float*)(smem + FOF_X2);
    const float* y2s = (const float*)(smem + FOF_Y2);
    const float* ws  = (const float*)(smem + FOF_W);
    float* rowsum = (float*)(smem + FOF_RS);

    float G1 = (float)g_scal[6], G2 = (float)g_scal[7];

    #pragma unroll
    for (int mf = 0; mf < 4; mf++) {
        int r0 = wr * 64 + mf * 16 + g;
        float x0 = x2s[r0], x1 = x2s[r0 + 8];
        float p0 = 0.f, p1 = 0.f;
        #pragma unroll
        for (int nf = 0; nf < 4; nf++) {
            int c0 = wc * 32 + nf * 8 + 2 * t;
            float y0 = y2s[c0], y1 = y2s[c0 + 1];
            float w0 = ws[c0],  w1 = ws[c0 + 1];
            float d00 = fmaxf(x0 + y0 - 2.f * acc[mf][nf][0], 0.f) * (1.f / DF);
            float d01 = fmaxf(x0 + y1 - 2.f * acc[mf][nf][1], 0.f) * (1.f / DF);
            float d10 = fmaxf(x1 + y0 - 2.f * acc[mf][nf][2], 0.f) * (1.f / DF);
            float d11 = fmaxf(x1 + y1 - 2.f * acc[mf][nf][3], 0.f) * (1.f / DF);
            p0 += (__expf(-G1 * d00) + __expf(-G2 * d00)) * w0
                + (__expf(-G1 * d01) + __expf(-G2 * d01)) * w1;
            p1 += (__expf(-G1 * d10) + __expf(-G2 * d10)) * w0
                + (__expf(-G1 * d11) + __expf(-G2 * d11)) * w1;
        }
        atomicAdd(&rowsum[r0], p0);
        atomicAdd(&rowsum[r0 + 8], p1);
    }
    __syncthreads();
    if (tid < TB) {
        float* Sout = ae ? g_Sae : g_Saa;
        atomicAdd(&Sout[row0 + tid], rowsum[tid]);
    }
}

// ---------------- final combine ----------------
__global__ void k_combine(const float* __restrict__ w, float* __restrict__ out) {
    int i = blockIdx.x * blockDim.x + threadIdx.x;
    if (i < NPTS) {
        float Ws  = (float)g_scal[0];
        float EWs = (float)g_scal[1];
        out[i] = (w[i] / Ws) * (g_Sae[i] / EWs - g_Saa[i] / Ws);
    }
}

// ---------------- host launcher ----------------
extern "C" void kernel_launch(void* const* d_in, const int* in_sizes, int n_in,
                              void* d_out, int out_size)
{
    const float* state   = (const float*)d_in[0];
    const float* action  = (const float*)d_in[1];
    const float* estate  = (const float*)d_in[2];
    const float* eaction = (const float*)d_in[3];
    const float* w       = (const float*)d_in[4];
    const float* ew      = (const float*)d_in[5];
    float* out = (float*)d_out;

    cudaFuncSetAttribute(k_hist_sampled, cudaFuncAttributeMaxDynamicSharedMemorySize, SMEM_HS);
    cudaFuncSetAttribute(k_refine_mma,   cudaFuncAttributeMaxDynamicSharedMemorySize, SMEM_RF);
    cudaFuncSetAttribute(k_final,        cudaFuncAttributeMaxDynamicSharedMemorySize, SMEM_FIN);

    dim3 ghs(NTILE, 4, 2);
    dim3 gfull(NTILE, NTILE, 2);

    k_cvt<<<2048, 256>>>(state, action, estate, eaction);
    k_wsum<<<1, 1024>>>(w, ew);

    k_hist_sampled<<<ghs, 256, SMEM_HS>>>(w, ew);
    k_scan0<<<2, 256>>>();

    k_refine_mma<<<gfull, 256, SMEM_RF>>>(w, ew);
    k_scanF<<<2, 1024>>>();

    k_final<<<gfull, 256, SMEM_FIN>>>(w, ew);

    k_combine<<<16, 256>>>(w, out);
}